// round 1
// baseline (speedup 1.0000x reference)
#include <cuda_runtime.h>

#define M_   64
#define L_   32
#define P_   100
#define NC_  400
#define TWO_PI_F 6.28318530717958647692f

struct Layer { float d, inv_a, inv_b, b2, rho, inv_rho; };

__device__ Layer g_layers[M_ * L_];
__device__ float g_rng[M_ * P_];
__device__ float g_e00[M_ * P_];

// ---------------------------------------------------------------------------
// Core: Thomson-Haskell 31-layer recursion for one (wvno, omega) point.
// Returns e[...,0] after the scan (matches _dltar4).
// ---------------------------------------------------------------------------
__device__ __forceinline__ float dltar4(float wvno, float omega, const Layer* lay) {
    float wvno2  = wvno * wvno;
    float inv_w  = __fdividef(1.0f, omega);
    float inv_w2 = inv_w * inv_w;

    // --- halfspace (layer L-1) initial vector ---
    Layer hl = lay[L_ - 1];
    {
        float xka = omega * hl.inv_a;
        float xkb = omega * hl.inv_b;
        float ra  = sqrtf(fabsf(wvno2 - xka * xka));
        float rb  = sqrtf(fabsf(wvno2 - xkb * xkb));
        float gammk = 2.0f * hl.b2 * inv_w2;
        float gam   = gammk * wvno2;
        float gamm1 = gam - 1.0f;
        float r     = hl.rho;
        float rarb  = ra * rb;
        float e0 = r * r * (gamm1 * gamm1 - gam * gammk * rarb);
        float e1 = -r * ra;
        float e2 = r * (gamm1 - gammk * rarb);
        float e3 = r * rb;
        float e4 = wvno2 - rarb;

        #pragma unroll 1
        for (int i = L_ - 2; i >= 0; --i) {
            Layer ly = lay[i];
            float dm    = ly.d;
            float xka_l = omega * ly.inv_a;
            float xkb_l = omega * ly.inv_b;
            float gammk_l = 2.0f * ly.b2 * inv_w2;
            float gam_l   = gammk_l * wvno2;
            float ra_l = sqrtf(fabsf(wvno2 - xka_l * xka_l));
            float rb_l = sqrtf(fabsf(wvno2 - xkb_l * xkb_l));
            float p = ra_l * dm;
            float q = rb_l * dm;

            // ---- _var ----
            float sinp, cosp_o; __sincosf(p, &sinp, &cosp_o);
            float sinq, cosq_o; __sincosf(q, &sinq, &cosq_o);
            float fac_p = (p < 16.0f) ? __expf(-2.0f * p) : 0.0f;
            float fac_q = (q < 16.0f) ? __expf(-2.0f * q) : 0.0f;
            float cosp_e = 0.5f * (1.0f + fac_p), sinp_e = 0.5f * (1.0f - fac_p);
            float cosq_e = 0.5f * (1.0f + fac_q), sinq_e = 0.5f * (1.0f - fac_q);
            float inv_ra = __fdividef(1.0f, (ra_l > 0.0f) ? ra_l : 1.0f);
            float inv_rb = __fdividef(1.0f, (rb_l > 0.0f) ? rb_l : 1.0f);
            bool lt_a = wvno < xka_l, gt_a = wvno > xka_l;
            bool lt_b = wvno < xkb_l, gt_b = wvno > xkb_l;
            float pex = gt_a ? p : 0.0f;
            float sex = gt_b ? q : 0.0f;
            float cosp = lt_a ? cosp_o : (gt_a ? cosp_e : 1.0f);
            float cosq = lt_b ? cosq_o : (gt_b ? cosq_e : 1.0f);
            float w = lt_a ? sinp * inv_ra : (gt_a ? sinp_e * inv_ra : dm);
            float x = lt_a ? -ra_l * sinp  : (gt_a ? ra_l * sinp_e  : 0.0f);
            float y = lt_b ? sinq * inv_rb : (gt_b ? sinq_e * inv_rb : dm);
            float z = lt_b ? -rb_l * sinq  : (gt_b ? rb_l * sinq_e  : 0.0f);
            float exa = pex + sex;
            float a0  = (exa < 60.0f) ? __expf(-exa) : 0.0f;
            float cpcq = cosp * cosq;
            float cpy  = cosp * y,  cpz = cosp * z;
            float cqw  = cosq * w,  cqx = cosq * x;
            float xy = x * y, xz = x * z, wy = w * y, wz = w * z;

            // ---- _dnka ----
            float gamm1_l = gam_l - 1.0f;
            float twgm1 = gam_l + gamm1_l;
            float gmgmk = gam_l * gammk_l;
            float gmgm1 = gam_l * gamm1_l;
            float gm1sq = gamm1_l * gamm1_l;
            float rho   = ly.rho,  rho_i  = ly.inv_rho;
            float rho2  = rho * rho;
            float rho_i2 = rho_i * rho_i;
            float a0pq = a0 - cpcq;
            float t    = -2.0f * wvno2;
            float c00 = cpcq - 2.0f * gmgm1 * a0pq - gmgmk * xz - wvno2 * gm1sq * wy;
            float c01 = (wvno2 * cpy - cqx) * rho_i;
            float c02 = -(twgm1 * a0pq + gammk_l * xz + wvno2 * gamm1_l * wy) * rho_i;
            float c03 = (cpz - wvno2 * cqw) * rho_i;
            float c04 = -(2.0f * wvno2 * a0pq + xz + wvno2 * wvno2 * wy) * rho_i2;
            float c10 = (gmgmk * cpz - gm1sq * cqw) * rho;
            float c11 = cpcq;
            float c12 = gammk_l * cpz - gamm1_l * cqw;
            float c13 = -wz;
            float c30 = (gm1sq * cpy - gmgmk * cqx) * rho;
            float c31 = -xy;
            float c32 = gamm1_l * cpy - gammk_l * cqx;
            float c40 = -(2.0f * gmgmk * gm1sq * a0pq + gmgmk * gmgmk * xz
                          + gm1sq * gm1sq * wy) * rho2;
            float c42 = -(gammk_l * gamm1_l * twgm1 * a0pq + gam_l * gammk_l * gammk_l * xz
                          + gamm1_l * gm1sq * wy) * rho;
            float c20 = t * c42, c21 = t * c32, c23 = t * c12, c24 = t * c02;
            float c22 = a0 + 2.0f * (cpcq - c00);

            // ---- ee = e @ ca  (ca row j listed above, ee[i] = sum_j e[j]*ca[j][i]) ----
            float ee0 = e0 * c00 + e1 * c10 + e2 * c20 + e3 * c30 + e4 * c40;
            float ee1 = e0 * c01 + e1 * c11 + e2 * c21 + e3 * c31 + e4 * c30;
            float ee2 = e0 * c02 + e1 * c12 + e2 * c22 + e3 * c32 + e4 * c42;
            float ee3 = e0 * c03 + e1 * c13 + e2 * c23 + e3 * c11 + e4 * c10;
            float ee4 = e0 * c04 + e1 * c03 + e2 * c24 + e3 * c01 + e4 * c00;

            float t1 = fmaxf(fmaxf(fabsf(ee0), fabsf(ee1)),
                             fmaxf(fmaxf(fabsf(ee2), fabsf(ee3)), fabsf(ee4)));
            t1 = (t1 < 1e-30f) ? 1.0f : t1;
            float ti = __fdividef(1.0f, t1);
            e0 = ee0 * ti; e1 = ee1 * ti; e2 = ee2 * ti; e3 = ee3 * ti; e4 = ee4 * ti;
        }
        return e0;
    }
}

// ---------------------------------------------------------------------------
// Prep: per (m, layer) derived constants (a, rho polynomials + reciprocals)
// ---------------------------------------------------------------------------
__global__ void prepKernel(const float* __restrict__ d, const float* __restrict__ b) {
    int i = blockIdx.x * blockDim.x + threadIdx.x;
    if (i >= M_ * L_) return;
    float bb = b[i];
    float b2 = bb * bb, b3 = b2 * bb, b4 = b2 * b2;
    float a = 0.9409f + 2.0947f * bb - 0.8206f * b2 + 0.2683f * b3 - 0.0251f * b4;
    float a2 = a * a, a3 = a2 * a, a4 = a2 * a2, a5 = a4 * a;
    float rho = 1.6612f * a - 0.4721f * a2 + 0.0671f * a3 - 0.0043f * a4 + 0.000106f * a5;
    Layer ly;
    ly.d = d[i];
    ly.inv_a = 1.0f / a;
    ly.inv_b = 1.0f / bb;
    ly.b2 = b2;
    ly.rho = rho;
    ly.inv_rho = 1.0f / rho;
    g_layers[i] = ly;
}

// ---------------------------------------------------------------------------
// Det grid: one block per (m,p); 128 threads stride over NC=400 trial C values.
// rng[m,p] = max_c det - min_c det (det never hits DRAM).
// ---------------------------------------------------------------------------
__global__ void __launch_bounds__(128) detKernel(const float* __restrict__ tlist,
                                                 const float* __restrict__ Clist) {
    __shared__ float shLay[L_ * 6];
    __shared__ float shC[NC_];
    __shared__ float red[64];
    int blk = blockIdx.x;          // m*P + p
    int m = blk / P_;
    const float* gl = reinterpret_cast<const float*>(&g_layers[m * L_]);
    for (int i = threadIdx.x; i < L_ * 6; i += blockDim.x) shLay[i] = gl[i];
    for (int i = threadIdx.x; i < NC_; i += blockDim.x) shC[i] = Clist[i];
    __syncthreads();

    float tval = tlist[blk];
    float omega_raw = TWO_PI_F / tval;
    float omega = fmaxf(omega_raw, 1e-4f);
    const Layer* lay = reinterpret_cast<const Layer*>(shLay);

    float mn = 3.4e38f, mx = -3.4e38f;
    for (int c = threadIdx.x; c < NC_; c += blockDim.x) {
        float wvno = omega_raw / shC[c];
        float det = dltar4(wvno, omega, lay);
        mn = fminf(mn, det);
        mx = fmaxf(mx, det);
    }
    #pragma unroll
    for (int o = 16; o > 0; o >>= 1) {
        mn = fminf(mn, __shfl_xor_sync(0xffffffffu, mn, o));
        mx = fmaxf(mx, __shfl_xor_sync(0xffffffffu, mx, o));
    }
    int wid = threadIdx.x >> 5;
    if ((threadIdx.x & 31) == 0) { red[wid] = mn; red[wid + 32] = mx; }
    __syncthreads();
    if (threadIdx.x == 0) {
        float amn = red[0], amx = red[32];
        for (int i = 1; i < (int)(blockDim.x >> 5); i++) {
            amn = fminf(amn, red[i]);
            amx = fmaxf(amx, red[i + 32]);
        }
        g_rng[blk] = amx - amn;
    }
}

// ---------------------------------------------------------------------------
// e00 grid: one thread per (m,p) at the actual trial velocity vlist.
// ---------------------------------------------------------------------------
__global__ void e00Kernel(const float* __restrict__ tlist, const float* __restrict__ vlist) {
    int idx = blockIdx.x * blockDim.x + threadIdx.x;
    if (idx >= M_ * P_) return;
    int m = idx / P_;
    float tval = tlist[idx];
    float omega_raw = TWO_PI_F / tval;
    float omega = fmaxf(omega_raw, 1e-4f);
    float wvno = omega_raw / vlist[idx];
    g_e00[idx] = dltar4(wvno, omega, &g_layers[m * L_]);
}

// ---------------------------------------------------------------------------
// Finalize: misfit transform + vertical-damping regularizer (horizontal = 0).
// ---------------------------------------------------------------------------
__global__ void __launch_bounds__(128) finalKernel(const float* __restrict__ b,
                                                   float* __restrict__ out) {
    __shared__ float red[4];
    int m = blockIdx.x;
    float acc = 0.0f;
    for (int p = threadIdx.x; p < P_; p += blockDim.x) {
        int idx = m * P_ + p;
        float v = g_e00[idx] / g_rng[idx];
        float pw = __expf(-2.3025850929940457f * fabsf(v));   // 0.1^|v|
        acc += fabsf(pw - 1.0f);
    }
    acc *= (1.0f / (float)P_);
    for (int i = threadIdx.x; i < L_; i += blockDim.x) {
        float bi = b[m * L_ + i];
        float val;
        if (i == 0)            val = bi - b[m * L_ + 1];
        else if (i == L_ - 1)  val = bi - b[m * L_ + L_ - 2];
        else                   val = 2.0f * bi - b[m * L_ + i - 1] - b[m * L_ + i + 1];
        acc += fabsf(val) * (1.0f / (float)L_);
    }
    #pragma unroll
    for (int o = 16; o > 0; o >>= 1) acc += __shfl_xor_sync(0xffffffffu, acc, o);
    int wid = threadIdx.x >> 5;
    if ((threadIdx.x & 31) == 0) red[wid] = acc;
    __syncthreads();
    if (threadIdx.x == 0) out[m] = red[0] + red[1] + red[2] + red[3];
}

// ---------------------------------------------------------------------------
extern "C" void kernel_launch(void* const* d_in, const int* in_sizes, int n_in,
                              void* d_out, int out_size) {
    const float* vlist = (const float*)d_in[0];
    const float* tlist = (const float*)d_in[1];
    const float* d     = (const float*)d_in[2];
    const float* b     = (const float*)d_in[3];
    const float* Clist = (const float*)d_in[4];
    float* out = (float*)d_out;

    prepKernel<<<(M_ * L_ + 255) / 256, 256>>>(d, b);
    detKernel<<<M_ * P_, 128>>>(tlist, Clist);
    e00Kernel<<<(M_ * P_ + 127) / 128, 128>>>(tlist, vlist);
    finalKernel<<<M_, 128>>>(b, out);
}

// round 2
// speedup vs baseline: 1.1211x; 1.1211x over previous
#include <cuda_runtime.h>

#define M_   64
#define L_   32
#define P_   100
#define NC_  400
#define NPAIR_ (NC_/2)
#define TWO_PI_F 6.28318530717958647692f

typedef unsigned long long ull;

struct Layer { float d, inv_a, inv_b, b2, rho, inv_rho; };

__device__ Layer g_layers[M_ * L_];
__device__ float g_rng[M_ * P_];
__device__ float g_e00[M_ * P_];

// ---------------------------------------------------------------------------
// Packed fp32x2 helpers (sm_100+: FFMA2 / FADD2 / FMUL2 via PTX .f32x2)
// ---------------------------------------------------------------------------
struct F2 { ull v; };
__device__ __forceinline__ F2 f2pk(float a, float b) {
    F2 r; asm("mov.b64 %0,{%1,%2};" : "=l"(r.v) : "f"(a), "f"(b)); return r;
}
__device__ __forceinline__ void f2up(F2 a, float& x, float& y) {
    asm("mov.b64 {%0,%1},%2;" : "=f"(x), "=f"(y) : "l"(a.v));
}
__device__ __forceinline__ F2 f2mul(F2 a, F2 b) {
    F2 r; asm("mul.rn.f32x2 %0,%1,%2;" : "=l"(r.v) : "l"(a.v), "l"(b.v)); return r;
}
__device__ __forceinline__ F2 f2add(F2 a, F2 b) {
    F2 r; asm("add.rn.f32x2 %0,%1,%2;" : "=l"(r.v) : "l"(a.v), "l"(b.v)); return r;
}
__device__ __forceinline__ F2 f2sub(F2 a, F2 b) {
    F2 r; asm("sub.rn.f32x2 %0,%1,%2;" : "=l"(r.v) : "l"(a.v), "l"(b.v)); return r;
}
__device__ __forceinline__ F2 f2fma(F2 a, F2 b, F2 c) {
    F2 r; asm("fma.rn.f32x2 %0,%1,%2,%3;" : "=l"(r.v) : "l"(a.v), "l"(b.v), "l"(c.v)); return r;
}
__device__ __forceinline__ float fsqrta(float x) {
    float r; asm("sqrt.approx.f32 %0,%1;" : "=f"(r) : "f"(x)); return r;
}
__device__ __forceinline__ ull dupf(float f) {
    unsigned u = __float_as_uint(f); return ((ull)u << 32) | (ull)u;
}

// ---------------------------------------------------------------------------
// _var for one lane (select-heavy, stays scalar)
// ---------------------------------------------------------------------------
__device__ __forceinline__ void var_lane(
    float wv, float wv2, float dm, float xka, float xka2, float xkb, float xkb2,
    float& cosp, float& cosq, float& w, float& x, float& y, float& z, float& a0)
{
    float ra = fsqrta(fabsf(wv2 - xka2));
    float rb = fsqrta(fabsf(wv2 - xkb2));
    float p = ra * dm, q = rb * dm;
    float sinp, cosp_o; __sincosf(p, &sinp, &cosp_o);
    float sinq, cosq_o; __sincosf(q, &sinq, &cosq_o);
    float fac_p = (p < 16.0f) ? __expf(-2.0f * p) : 0.0f;
    float fac_q = (q < 16.0f) ? __expf(-2.0f * q) : 0.0f;
    float cosp_e = 0.5f * (1.0f + fac_p), sinp_e = 0.5f * (1.0f - fac_p);
    float cosq_e = 0.5f * (1.0f + fac_q), sinq_e = 0.5f * (1.0f - fac_q);
    float inv_ra = __fdividef(1.0f, ra > 0.0f ? ra : 1.0f);
    float inv_rb = __fdividef(1.0f, rb > 0.0f ? rb : 1.0f);
    bool lt_a = wv < xka, gt_a = wv > xka;
    bool lt_b = wv < xkb, gt_b = wv > xkb;
    float pex = gt_a ? p : 0.0f;
    float sex = gt_b ? q : 0.0f;
    cosp = lt_a ? cosp_o : (gt_a ? cosp_e : 1.0f);
    cosq = lt_b ? cosq_o : (gt_b ? cosq_e : 1.0f);
    w = lt_a ? sinp * inv_ra : (gt_a ? sinp_e * inv_ra : dm);
    x = lt_a ? -ra * sinp    : (gt_a ? ra * sinp_e    : 0.0f);
    y = lt_b ? sinq * inv_rb : (gt_b ? sinq_e * inv_rb : dm);
    z = lt_b ? -rb * sinq    : (gt_b ? rb * sinq_e    : 0.0f);
    float exa = pex + sex;
    a0 = (exa < 60.0f) ? __expf(-exa) : 0.0f;
}

__device__ __forceinline__ void half_lane(
    float wv2, float xka2h, float xkb2h, float gmkh, float rhoh,
    float& e0, float& e1, float& e2, float& e3, float& e4)
{
    float ra = fsqrta(fabsf(wv2 - xka2h));
    float rb = fsqrta(fabsf(wv2 - xkb2h));
    float gam = gmkh * wv2, gamm1 = gam - 1.0f;
    float rarb = ra * rb;
    e0 = rhoh * rhoh * (gamm1 * gamm1 - gam * gmkh * rarb);
    e1 = -rhoh * ra;
    e2 = rhoh * (gamm1 - gmkh * rarb);
    e3 = rhoh * rb;
    e4 = wv2 - rarb;
}

// ---------------------------------------------------------------------------
// Scalar dltar4 (kept for the small e00 grid)
// ---------------------------------------------------------------------------
__device__ __forceinline__ float dltar4_scalar(float wvno, float omega, const Layer* lay) {
    float wvno2 = wvno * wvno;
    float inv_w = __fdividef(1.0f, omega);
    float inv_w2 = inv_w * inv_w;
    Layer hl = lay[L_ - 1];
    float xka = omega * hl.inv_a, xkb = omega * hl.inv_b;
    float gmk = 2.0f * hl.b2 * inv_w2;
    float e0, e1, e2, e3, e4;
    half_lane(wvno2, xka * xka, xkb * xkb, gmk, hl.rho, e0, e1, e2, e3, e4);

    #pragma unroll 1
    for (int i = L_ - 2; i >= 0; --i) {
        Layer ly = lay[i];
        float dm = ly.d;
        float xka_l = omega * ly.inv_a, xkb_l = omega * ly.inv_b;
        float gammk = 2.0f * ly.b2 * inv_w2;
        float gam = gammk * wvno2;
        float cosp, cosq, w, x, y, z, a0;
        var_lane(wvno, wvno2, dm, xka_l, xka_l * xka_l, xkb_l, xkb_l * xkb_l,
                 cosp, cosq, w, x, y, z, a0);
        float cpcq = cosp * cosq;
        float cpy = cosp * y, cpz = cosp * z, cqw = cosq * w, cqx = cosq * x;
        float xy = x * y, xz = x * z, wy = w * y, wz = w * z;
        float gamm1 = gam - 1.0f;
        float twgm1 = gam + gamm1;
        float gmgmk = gam * gammk;
        float gmgm1 = gam * gamm1;
        float gm1sq = gamm1 * gamm1;
        float rho = ly.rho, rho_i = ly.inv_rho;
        float a0pq = a0 - cpcq;
        float t = -2.0f * wvno2;
        float c00 = cpcq - 2.0f * gmgm1 * a0pq - gmgmk * xz - wvno2 * gm1sq * wy;
        float c01 = (wvno2 * cpy - cqx) * rho_i;
        float c02 = -(twgm1 * a0pq + gammk * xz + wvno2 * gamm1 * wy) * rho_i;
        float c03 = (cpz - wvno2 * cqw) * rho_i;
        float c04 = -(2.0f * wvno2 * a0pq + xz + wvno2 * wvno2 * wy) * rho_i * rho_i;
        float c10 = (gmgmk * cpz - gm1sq * cqw) * rho;
        float c12 = gammk * cpz - gamm1 * cqw;
        float c30 = (gm1sq * cpy - gmgmk * cqx) * rho;
        float c32 = gamm1 * cpy - gammk * cqx;
        float c40 = -(2.0f * gmgmk * gm1sq * a0pq + gmgmk * gmgmk * xz + gm1sq * gm1sq * wy) * rho * rho;
        float c42 = -(gammk * gamm1 * twgm1 * a0pq + gam * gammk * gammk * xz + gamm1 * gm1sq * wy) * rho;
        float c20 = t * c42, c21 = t * c32, c23 = t * c12, c24 = t * c02;
        float c22 = a0 + 2.0f * (cpcq - c00);
        float ee0 = e0 * c00 + e1 * c10 + e2 * c20 + e3 * c30 + e4 * c40;
        float ee1 = e0 * c01 + e1 * cpcq + e2 * c21 - e3 * xy + e4 * c30;
        float ee2 = e0 * c02 + e1 * c12 + e2 * c22 + e3 * c32 + e4 * c42;
        float ee3 = e0 * c03 - e1 * wz + e2 * c23 + e3 * cpcq + e4 * c10;
        float ee4 = e0 * c04 + e1 * c03 + e2 * c24 + e3 * c01 + e4 * c00;
        float t1 = fmaxf(fmaxf(fabsf(ee0), fabsf(ee1)),
                         fmaxf(fmaxf(fabsf(ee2), fabsf(ee3)), fabsf(ee4)));
        t1 = (t1 < 1e-30f) ? 1.0f : t1;
        float ti = __fdividef(1.0f, t1);
        e0 = ee0 * ti; e1 = ee1 * ti; e2 = ee2 * ti; e3 = ee3 * ti; e4 = ee4 * ti;
    }
    return e0;
}

// ---------------------------------------------------------------------------
__global__ void prepKernel(const float* __restrict__ d, const float* __restrict__ b) {
    int i = blockIdx.x * blockDim.x + threadIdx.x;
    if (i >= M_ * L_) return;
    float bb = b[i];
    float b2 = bb * bb, b3 = b2 * bb, b4 = b2 * b2;
    float a = 0.9409f + 2.0947f * bb - 0.8206f * b2 + 0.2683f * b3 - 0.0251f * b4;
    float a2 = a * a, a3 = a2 * a, a4 = a2 * a2, a5 = a4 * a;
    float rho = 1.6612f * a - 0.4721f * a2 + 0.0671f * a3 - 0.0043f * a4 + 0.000106f * a5;
    Layer ly;
    ly.d = d[i]; ly.inv_a = 1.0f / a; ly.inv_b = 1.0f / bb;
    ly.b2 = b2;  ly.rho = rho;        ly.inv_rho = 1.0f / rho;
    g_layers[i] = ly;
}

__global__ void dummyKernel() {}   // ncu capture alignment: shifts -s 5 slot onto detKernel

// ---------------------------------------------------------------------------
// Det grid: one block per (m,p); each thread handles a PAIR of C values using
// packed fp32x2 math for the dnka build + matvec. rng = max - min over C.
// ---------------------------------------------------------------------------
__global__ void __launch_bounds__(128) detKernel(const float* __restrict__ tlist,
                                                 const float* __restrict__ Clist) {
    __shared__ float sD[L_], sXka[L_], sXka2[L_], sXkb[L_], sXkb2[L_], sGmk[L_], sRho[L_];
    __shared__ ull pGmk[L_], pRho[L_], pNRho[L_], pNRho2[L_], pRhoI[L_], pNRhoI[L_], pNRhoI2[L_];
    __shared__ float shC[NC_];
    __shared__ float red[64];

    int blk = blockIdx.x;                   // m*P + p
    int m = blk / P_;
    float tval = tlist[blk];
    float omega_raw = TWO_PI_F / tval;
    float omega = fmaxf(omega_raw, 1e-4f);

    if (threadIdx.x < L_) {
        int i = threadIdx.x;
        Layer ly = g_layers[m * L_ + i];
        float xka = omega * ly.inv_a, xkb = omega * ly.inv_b;
        float iw = __fdividef(1.0f, omega);
        float gmk = 2.0f * ly.b2 * iw * iw;
        sD[i] = ly.d; sXka[i] = xka; sXka2[i] = xka * xka;
        sXkb[i] = xkb; sXkb2[i] = xkb * xkb; sGmk[i] = gmk; sRho[i] = ly.rho;
        pGmk[i]    = dupf(gmk);
        pRho[i]    = dupf(ly.rho);
        pNRho[i]   = dupf(-ly.rho);
        pNRho2[i]  = dupf(-ly.rho * ly.rho);
        pRhoI[i]   = dupf(ly.inv_rho);
        pNRhoI[i]  = dupf(-ly.inv_rho);
        pNRhoI2[i] = dupf(-ly.inv_rho * ly.inv_rho);
    }
    for (int i = threadIdx.x; i < NC_; i += blockDim.x) shC[i] = Clist[i];
    __syncthreads();

    float gmk_h = sGmk[L_ - 1], rho_h = sRho[L_ - 1];
    float xka2_h = sXka2[L_ - 1], xkb2_h = sXkb2[L_ - 1];

    float mn = 3.4e38f, mx = -3.4e38f;

    #pragma unroll 1
    for (int pc = threadIdx.x; pc < NPAIR_; pc += 128) {
        float wv0 = __fdividef(omega_raw, shC[2 * pc]);
        float wv1 = __fdividef(omega_raw, shC[2 * pc + 1]);
        float wv20 = wv0 * wv0, wv21 = wv1 * wv1;
        F2 W2 = f2pk(wv20, wv21);
        F2 Tp = f2pk(-2.0f * wv20, -2.0f * wv21);
        F2 ONE = f2pk(1.0f, 1.0f);

        float h0a, h1a, h2a, h3a, h4a, h0b, h1b, h2b, h3b, h4b;
        half_lane(wv20, xka2_h, xkb2_h, gmk_h, rho_h, h0a, h1a, h2a, h3a, h4a);
        half_lane(wv21, xka2_h, xkb2_h, gmk_h, rho_h, h0b, h1b, h2b, h3b, h4b);
        F2 E0 = f2pk(h0a, h0b), E1 = f2pk(h1a, h1b), E2 = f2pk(h2a, h2b);
        F2 E3 = f2pk(h3a, h3b), E4 = f2pk(h4a, h4b);

        #pragma unroll 1
        for (int i = L_ - 2; i >= 0; --i) {
            float dm = sD[i], xka = sXka[i], xka2 = sXka2[i], xkb = sXkb[i], xkb2 = sXkb2[i];
            float cp0, cq0, w0, x0, y0, z0, a00;
            float cp1, cq1, w1, x1, y1, z1, a01;
            var_lane(wv0, wv20, dm, xka, xka2, xkb, xkb2, cp0, cq0, w0, x0, y0, z0, a00);
            var_lane(wv1, wv21, dm, xka, xka2, xkb, xkb2, cp1, cq1, w1, x1, y1, z1, a01);
            F2 Cp = f2pk(cp0, cp1), Cq = f2pk(cq0, cq1);
            F2 W = f2pk(w0, w1), X = f2pk(x0, x1), Y = f2pk(y0, y1), Z = f2pk(z0, z1);
            F2 A0 = f2pk(a00, a01);

            F2 Gmk;    Gmk.v    = pGmk[i];
            F2 Rho;    Rho.v    = pRho[i];
            F2 NRho;   NRho.v   = pNRho[i];
            F2 NRho2;  NRho2.v  = pNRho2[i];
            F2 RhoI;   RhoI.v   = pRhoI[i];
            F2 NRhoI;  NRhoI.v  = pNRhoI[i];
            F2 NRhoI2; NRhoI2.v = pNRhoI2[i];

            F2 Gam  = f2mul(Gmk, W2);
            F2 cpcq = f2mul(Cp, Cq);
            F2 cpy = f2mul(Cp, Y), cpz = f2mul(Cp, Z);
            F2 cqw = f2mul(Cq, W), cqx = f2mul(Cq, X);
            F2 xy = f2mul(X, Y), xz = f2mul(X, Z), wy = f2mul(W, Y), wz = f2mul(W, Z);
            F2 gamm1 = f2sub(Gam, ONE);
            F2 twgm1 = f2add(Gam, gamm1);
            F2 gmgmk = f2mul(Gam, Gmk);
            F2 gmgm1 = f2mul(Gam, gamm1);
            F2 gm1sq = f2mul(gamm1, gamm1);
            F2 a0pq  = f2sub(A0, cpcq);
            F2 A2    = f2add(a0pq, a0pq);      // 2*a0pq
            F2 w2wy  = f2mul(W2, wy);

            F2 u = f2fma(gm1sq, w2wy, f2mul(gmgmk, xz));
            u = f2fma(gmgm1, A2, u);
            F2 c00 = f2sub(cpcq, u);
            F2 c01 = f2mul(f2sub(f2mul(W2, cpy), cqx), RhoI);
            F2 v = f2fma(Gmk, xz, f2mul(gamm1, w2wy));
            v = f2fma(twgm1, a0pq, v);
            F2 c02 = f2mul(v, NRhoI);
            F2 c03 = f2mul(f2sub(cpz, f2mul(W2, cqw)), RhoI);
            F2 s = f2fma(W2, A2, xz);
            s = f2fma(W2, w2wy, s);
            F2 c04 = f2mul(s, NRhoI2);
            F2 c10 = f2mul(f2sub(f2mul(gmgmk, cpz), f2mul(gm1sq, cqw)), Rho);
            F2 c12 = f2sub(f2mul(Gmk, cpz), f2mul(gamm1, cqw));
            F2 c30 = f2mul(f2sub(f2mul(gm1sq, cpy), f2mul(gmgmk, cqx)), Rho);
            F2 c32 = f2sub(f2mul(gamm1, cpy), f2mul(Gmk, cqx));
            F2 gg   = f2mul(gmgmk, gm1sq);
            F2 gmk2 = f2mul(gmgmk, gmgmk);
            F2 g1q  = f2mul(gm1sq, gm1sq);
            F2 hh = f2fma(gmk2, xz, f2mul(g1q, wy));
            hh = f2fma(gg, A2, hh);
            F2 c40 = f2mul(hh, NRho2);
            F2 k1 = f2mul(f2mul(Gmk, gamm1), twgm1);
            F2 k2 = f2mul(gmgmk, Gmk);
            F2 k3 = f2mul(gamm1, gm1sq);
            F2 v2 = f2fma(k2, xz, f2mul(k3, wy));
            v2 = f2fma(k1, a0pq, v2);
            F2 c42 = f2mul(v2, NRho);
            F2 c20 = f2mul(Tp, c42), c21 = f2mul(Tp, c32);
            F2 c23 = f2mul(Tp, c12), c24 = f2mul(Tp, c02);
            F2 dd = f2sub(cpcq, c00);
            F2 c22 = f2add(A0, f2add(dd, dd));

            F2 ee0 = f2fma(E0, c00, f2fma(E1, c10, f2fma(E2, c20, f2fma(E3, c30, f2mul(E4, c40)))));
            F2 ee1 = f2fma(E0, c01, f2fma(E1, cpcq, f2fma(E2, c21, f2sub(f2mul(E4, c30), f2mul(E3, xy)))));
            F2 ee2 = f2fma(E0, c02, f2fma(E1, c12, f2fma(E2, c22, f2fma(E3, c32, f2mul(E4, c42)))));
            F2 ee3 = f2fma(E0, c03, f2fma(E2, c23, f2fma(E3, cpcq, f2sub(f2mul(E4, c10), f2mul(E1, wz)))));
            F2 ee4 = f2fma(E0, c04, f2fma(E1, c03, f2fma(E2, c24, f2fma(E3, c01, f2mul(E4, c00)))));

            float g0, q0, g1, q1, g2, q2, g3, q3, g4, q4;
            f2up(ee0, g0, q0); f2up(ee1, g1, q1); f2up(ee2, g2, q2);
            f2up(ee3, g3, q3); f2up(ee4, g4, q4);
            float t1a = fmaxf(fmaxf(fabsf(g0), fabsf(g1)),
                              fmaxf(fmaxf(fabsf(g2), fabsf(g3)), fabsf(g4)));
            float t1b = fmaxf(fmaxf(fabsf(q0), fabsf(q1)),
                              fmaxf(fmaxf(fabsf(q2), fabsf(q3)), fabsf(q4)));
            t1a = (t1a < 1e-30f) ? 1.0f : t1a;
            t1b = (t1b < 1e-30f) ? 1.0f : t1b;
            F2 Ti = f2pk(__fdividef(1.0f, t1a), __fdividef(1.0f, t1b));
            E0 = f2mul(ee0, Ti); E1 = f2mul(ee1, Ti); E2 = f2mul(ee2, Ti);
            E3 = f2mul(ee3, Ti); E4 = f2mul(ee4, Ti);
        }
        float d0, d1;
        f2up(E0, d0, d1);
        mn = fminf(mn, fminf(d0, d1));
        mx = fmaxf(mx, fmaxf(d0, d1));
    }

    #pragma unroll
    for (int o = 16; o > 0; o >>= 1) {
        mn = fminf(mn, __shfl_xor_sync(0xffffffffu, mn, o));
        mx = fmaxf(mx, __shfl_xor_sync(0xffffffffu, mx, o));
    }
    int wid = threadIdx.x >> 5;
    if ((threadIdx.x & 31) == 0) { red[wid] = mn; red[wid + 32] = mx; }
    __syncthreads();
    if (threadIdx.x == 0) {
        float amn = red[0], amx = red[32];
        #pragma unroll
        for (int i = 1; i < 4; i++) {
            amn = fminf(amn, red[i]);
            amx = fmaxf(amx, red[i + 32]);
        }
        g_rng[blk] = amx - amn;
    }
}

// ---------------------------------------------------------------------------
__global__ void e00Kernel(const float* __restrict__ tlist, const float* __restrict__ vlist) {
    int idx = blockIdx.x * blockDim.x + threadIdx.x;
    if (idx >= M_ * P_) return;
    int m = idx / P_;
    float tval = tlist[idx];
    float omega_raw = TWO_PI_F / tval;
    float omega = fmaxf(omega_raw, 1e-4f);
    float wvno = omega_raw / vlist[idx];
    g_e00[idx] = dltar4_scalar(wvno, omega, &g_layers[m * L_]);
}

// ---------------------------------------------------------------------------
__global__ void __launch_bounds__(128) finalKernel(const float* __restrict__ b,
                                                   float* __restrict__ out) {
    __shared__ float red[4];
    int m = blockIdx.x;
    float acc = 0.0f;
    for (int p = threadIdx.x; p < P_; p += blockDim.x) {
        int idx = m * P_ + p;
        float v = g_e00[idx] / g_rng[idx];
        float pw = __expf(-2.3025850929940457f * fabsf(v));   // 0.1^|v|
        acc += fabsf(pw - 1.0f);
    }
    acc *= (1.0f / (float)P_);
    for (int i = threadIdx.x; i < L_; i += blockDim.x) {
        float bi = b[m * L_ + i];
        float val;
        if (i == 0)            val = bi - b[m * L_ + 1];
        else if (i == L_ - 1)  val = bi - b[m * L_ + L_ - 2];
        else                   val = 2.0f * bi - b[m * L_ + i - 1] - b[m * L_ + i + 1];
        acc += fabsf(val) * (1.0f / (float)L_);
    }
    #pragma unroll
    for (int o = 16; o > 0; o >>= 1) acc += __shfl_xor_sync(0xffffffffu, acc, o);
    int wid = threadIdx.x >> 5;
    if ((threadIdx.x & 31) == 0) red[wid] = acc;
    __syncthreads();
    if (threadIdx.x == 0) out[m] = red[0] + red[1] + red[2] + red[3];
}

// ---------------------------------------------------------------------------
extern "C" void kernel_launch(void* const* d_in, const int* in_sizes, int n_in,
                              void* d_out, int out_size) {
    const float* vlist = (const float*)d_in[0];
    const float* tlist = (const float*)d_in[1];
    const float* d     = (const float*)d_in[2];
    const float* b     = (const float*)d_in[3];
    const float* Clist = (const float*)d_in[4];
    float* out = (float*)d_out;

    dummyKernel<<<1, 32>>>();
    dummyKernel<<<1, 32>>>();
    prepKernel<<<(M_ * L_ + 255) / 256, 256>>>(d, b);
    detKernel<<<M_ * P_, 128>>>(tlist, Clist);
    e00Kernel<<<(M_ * P_ + 127) / 128, 128>>>(tlist, vlist);
    finalKernel<<<M_, 128>>>(b, out);
}

// round 3
// speedup vs baseline: 1.1982x; 1.0688x over previous
#include <cuda_runtime.h>

#define M_   64
#define L_   32
#define P_   100
#define NC_  400
#define NPAIR_ (NC_/2)
#define TWO_PI_F 6.28318530717958647692f

typedef unsigned long long ull;

struct Layer { float d, inv_a, inv_b, b2, rho, inv_rho; };

__device__ Layer g_layers[M_ * L_];
__device__ float g_rng[M_ * P_];
__device__ float g_e00[M_ * P_];

// ---------------------------------------------------------------------------
// Packed fp32x2 helpers
// ---------------------------------------------------------------------------
struct F2 { ull v; };
__device__ __forceinline__ F2 f2pk(float a, float b) {
    F2 r; asm("mov.b64 %0,{%1,%2};" : "=l"(r.v) : "f"(a), "f"(b)); return r;
}
__device__ __forceinline__ void f2up(F2 a, float& x, float& y) {
    asm("mov.b64 {%0,%1},%2;" : "=f"(x), "=f"(y) : "l"(a.v));
}
__device__ __forceinline__ F2 f2mul(F2 a, F2 b) {
    F2 r; asm("mul.rn.f32x2 %0,%1,%2;" : "=l"(r.v) : "l"(a.v), "l"(b.v)); return r;
}
__device__ __forceinline__ F2 f2add(F2 a, F2 b) {
    F2 r; asm("add.rn.f32x2 %0,%1,%2;" : "=l"(r.v) : "l"(a.v), "l"(b.v)); return r;
}
__device__ __forceinline__ F2 f2sub(F2 a, F2 b) {
    F2 r; asm("sub.rn.f32x2 %0,%1,%2;" : "=l"(r.v) : "l"(a.v), "l"(b.v)); return r;
}
__device__ __forceinline__ F2 f2fma(F2 a, F2 b, F2 c) {
    F2 r; asm("fma.rn.f32x2 %0,%1,%2,%3;" : "=l"(r.v) : "l"(a.v), "l"(b.v), "l"(c.v)); return r;
}
__device__ __forceinline__ float fsqrta(float x) {
    float r; asm("sqrt.approx.f32 %0,%1;" : "=f"(r) : "f"(x)); return r;
}
__device__ __forceinline__ ull dupf(float f) {
    unsigned u = __float_as_uint(f); return ((ull)u << 32) | (ull)u;
}

// ---------------------------------------------------------------------------
// _var for one lane (select-trimmed; eq-case folded into gt formulas where valid)
// ---------------------------------------------------------------------------
__device__ __forceinline__ void var_lane(
    float wv, float wv2, float dm, float xka, float xka2, float xkb, float xkb2,
    float& cosp, float& cosq, float& w, float& x, float& y, float& z, float& a0)
{
    float ra = fsqrta(fabsf(wv2 - xka2));
    float rb = fsqrta(fabsf(wv2 - xkb2));
    float p = ra * dm, q = rb * dm;
    float sinp, cosp_o; __sincosf(p, &sinp, &cosp_o);
    float sinq, cosq_o; __sincosf(q, &sinq, &cosq_o);
    float fac_p = (p < 16.0f) ? __expf(-2.0f * p) : 0.0f;
    float fac_q = (q < 16.0f) ? __expf(-2.0f * q) : 0.0f;
    float cosp_e = 0.5f * (1.0f + fac_p), sinp_e = 0.5f * (1.0f - fac_p);
    float cosq_e = 0.5f * (1.0f + fac_q), sinq_e = 0.5f * (1.0f - fac_q);
    float inv_ra = __fdividef(1.0f, ra > 0.0f ? ra : 1.0f);
    float inv_rb = __fdividef(1.0f, rb > 0.0f ? rb : 1.0f);
    bool lt_a = wv < xka, gt_a = wv > xka;
    bool lt_b = wv < xkb, gt_b = wv > xkb;
    // eq-case: p = 0 -> cosp_e = 1, ra*sinp_e = 0, pex = p = 0: gt formulas valid.
    float pex = lt_a ? 0.0f : p;
    float sex = lt_b ? 0.0f : q;
    cosp = lt_a ? cosp_o : cosp_e;
    cosq = lt_b ? cosq_o : cosq_e;
    w = lt_a ? sinp * inv_ra : (gt_a ? sinp_e * inv_ra : dm);
    x = lt_a ? -ra * sinp    : ra * sinp_e;
    y = lt_b ? sinq * inv_rb : (gt_b ? sinq_e * inv_rb : dm);
    z = lt_b ? -rb * sinq    : rb * sinq_e;
    float exa = pex + sex;
    a0 = (exa < 60.0f) ? __expf(-exa) : 0.0f;
}

__device__ __forceinline__ void half_lane(
    float wv2, float xka2h, float xkb2h, float gmkh, float rhoh,
    float& e0, float& e1, float& e2, float& e3, float& e4)
{
    float ra = fsqrta(fabsf(wv2 - xka2h));
    float rb = fsqrta(fabsf(wv2 - xkb2h));
    float gam = gmkh * wv2, gamm1 = gam - 1.0f;
    float rarb = ra * rb;
    e0 = rhoh * rhoh * (gamm1 * gamm1 - gam * gmkh * rarb);
    e1 = -rhoh * ra;
    e2 = rhoh * (gamm1 - gmkh * rarb);
    e3 = rhoh * rb;
    e4 = wv2 - rarb;
}

// ---------------------------------------------------------------------------
__global__ void prepKernel(const float* __restrict__ d, const float* __restrict__ b) {
    int i = blockIdx.x * blockDim.x + threadIdx.x;
    if (i >= M_ * L_) return;
    float bb = b[i];
    float b2 = bb * bb, b3 = b2 * bb, b4 = b2 * b2;
    float a = 0.9409f + 2.0947f * bb - 0.8206f * b2 + 0.2683f * b3 - 0.0251f * b4;
    float a2 = a * a, a3 = a2 * a, a4 = a2 * a2, a5 = a4 * a;
    float rho = 1.6612f * a - 0.4721f * a2 + 0.0671f * a3 - 0.0043f * a4 + 0.000106f * a5;
    Layer ly;
    ly.d = d[i]; ly.inv_a = 1.0f / a; ly.inv_b = 1.0f / bb;
    ly.b2 = b2;  ly.rho = rho;        ly.inv_rho = 1.0f / rho;
    g_layers[i] = ly;
}

__global__ void dummyKernel() {}   // ncu capture alignment

// ---------------------------------------------------------------------------
// Det grid + folded e00: one block per (m,p).
// Work items: pc in [0,200) = C-pairs (min/max reduced); pc == 200 = e00 point.
// Normalization every 2nd layer (scale-invariant; final layer always normed).
// ---------------------------------------------------------------------------
__global__ void __launch_bounds__(128, 6) detKernel(const float* __restrict__ tlist,
                                                    const float* __restrict__ Clist,
                                                    const float* __restrict__ vlist) {
    __shared__ float sD[L_], sXka[L_], sXka2[L_], sXkb[L_], sXkb2[L_], sGmk[L_], sRho[L_];
    __shared__ ull pGmk[L_], pRho[L_], pNRho[L_], pNRho2[L_], pRhoI[L_], pNRhoI[L_], pNRhoI2[L_];
    __shared__ float shC[NC_];
    __shared__ float red[64];

    int blk = blockIdx.x;                   // m*P + p
    int m = blk / P_;
    float tval = tlist[blk];
    float omega_raw = TWO_PI_F / tval;
    float omega = fmaxf(omega_raw, 1e-4f);
    float vblk = vlist[blk];

    if (threadIdx.x < L_) {
        int i = threadIdx.x;
        Layer ly = g_layers[m * L_ + i];
        float xka = omega * ly.inv_a, xkb = omega * ly.inv_b;
        float iw = __fdividef(1.0f, omega);
        float gmk = 2.0f * ly.b2 * iw * iw;
        sD[i] = ly.d; sXka[i] = xka; sXka2[i] = xka * xka;
        sXkb[i] = xkb; sXkb2[i] = xkb * xkb; sGmk[i] = gmk; sRho[i] = ly.rho;
        pGmk[i]    = dupf(gmk);
        pRho[i]    = dupf(ly.rho);
        pNRho[i]   = dupf(-ly.rho);
        pNRho2[i]  = dupf(-ly.rho * ly.rho);
        pRhoI[i]   = dupf(ly.inv_rho);
        pNRhoI[i]  = dupf(-ly.inv_rho);
        pNRhoI2[i] = dupf(-ly.inv_rho * ly.inv_rho);
    }
    for (int i = threadIdx.x; i < NC_; i += blockDim.x) shC[i] = Clist[i];
    __syncthreads();

    float gmk_h = sGmk[L_ - 1], rho_h = sRho[L_ - 1];
    float xka2_h = sXka2[L_ - 1], xkb2_h = sXkb2[L_ - 1];

    float mn = 3.4e38f, mx = -3.4e38f;

    #pragma unroll 1
    for (int pc = threadIdx.x; pc <= NPAIR_; pc += 128) {
        bool is_e00 = (pc == NPAIR_);
        int i0 = is_e00 ? 0 : 2 * pc;
        float den0 = is_e00 ? vblk : shC[i0];
        float den1 = is_e00 ? vblk : shC[i0 + 1];
        float wv0 = __fdividef(omega_raw, den0);
        float wv1 = __fdividef(omega_raw, den1);
        float wv20 = wv0 * wv0, wv21 = wv1 * wv1;
        F2 W2 = f2pk(wv20, wv21);
        F2 Tp = f2pk(-2.0f * wv20, -2.0f * wv21);
        F2 ONE = f2pk(1.0f, 1.0f);

        float h0a, h1a, h2a, h3a, h4a, h0b, h1b, h2b, h3b, h4b;
        half_lane(wv20, xka2_h, xkb2_h, gmk_h, rho_h, h0a, h1a, h2a, h3a, h4a);
        half_lane(wv21, xka2_h, xkb2_h, gmk_h, rho_h, h0b, h1b, h2b, h3b, h4b);
        F2 E0 = f2pk(h0a, h0b), E1 = f2pk(h1a, h1b), E2 = f2pk(h2a, h2b);
        F2 E3 = f2pk(h3a, h3b), E4 = f2pk(h4a, h4b);

        // one layer update; NORM = apply max-abs normalization afterward
        auto step = [&](int i, bool do_norm) {
            float dm = sD[i], xka = sXka[i], xka2 = sXka2[i], xkb = sXkb[i], xkb2 = sXkb2[i];
            float cp0, cq0, w0, x0, y0, z0, a00;
            float cp1, cq1, w1, x1, y1, z1, a01;
            var_lane(wv0, wv20, dm, xka, xka2, xkb, xkb2, cp0, cq0, w0, x0, y0, z0, a00);
            var_lane(wv1, wv21, dm, xka, xka2, xkb, xkb2, cp1, cq1, w1, x1, y1, z1, a01);
            F2 Cp = f2pk(cp0, cp1), Cq = f2pk(cq0, cq1);
            F2 W = f2pk(w0, w1), X = f2pk(x0, x1), Y = f2pk(y0, y1), Z = f2pk(z0, z1);
            F2 A0 = f2pk(a00, a01);

            F2 Gmk;    Gmk.v    = pGmk[i];
            F2 Rho;    Rho.v    = pRho[i];
            F2 NRho;   NRho.v   = pNRho[i];
            F2 NRho2;  NRho2.v  = pNRho2[i];
            F2 RhoI;   RhoI.v   = pRhoI[i];
            F2 NRhoI;  NRhoI.v  = pNRhoI[i];
            F2 NRhoI2; NRhoI2.v = pNRhoI2[i];

            F2 Gam  = f2mul(Gmk, W2);
            F2 cpcq = f2mul(Cp, Cq);
            F2 cpy = f2mul(Cp, Y), cpz = f2mul(Cp, Z);
            F2 cqw = f2mul(Cq, W), cqx = f2mul(Cq, X);
            F2 xy = f2mul(X, Y), xz = f2mul(X, Z), wy = f2mul(W, Y), wz = f2mul(W, Z);
            F2 gamm1 = f2sub(Gam, ONE);
            F2 twgm1 = f2add(Gam, gamm1);
            F2 gmgmk = f2mul(Gam, Gmk);
            F2 gmgm1 = f2mul(Gam, gamm1);
            F2 gm1sq = f2mul(gamm1, gamm1);
            F2 a0pq  = f2sub(A0, cpcq);
            F2 A2    = f2add(a0pq, a0pq);
            F2 w2wy  = f2mul(W2, wy);

            F2 u = f2fma(gm1sq, w2wy, f2mul(gmgmk, xz));
            u = f2fma(gmgm1, A2, u);
            F2 c00 = f2sub(cpcq, u);
            F2 c01 = f2mul(f2sub(f2mul(W2, cpy), cqx), RhoI);
            F2 v = f2fma(Gmk, xz, f2mul(gamm1, w2wy));
            v = f2fma(twgm1, a0pq, v);
            F2 c02 = f2mul(v, NRhoI);
            F2 c03 = f2mul(f2sub(cpz, f2mul(W2, cqw)), RhoI);
            F2 s = f2fma(W2, A2, xz);
            s = f2fma(W2, w2wy, s);
            F2 c04 = f2mul(s, NRhoI2);
            F2 c10 = f2mul(f2sub(f2mul(gmgmk, cpz), f2mul(gm1sq, cqw)), Rho);
            F2 c12 = f2sub(f2mul(Gmk, cpz), f2mul(gamm1, cqw));
            F2 c30 = f2mul(f2sub(f2mul(gm1sq, cpy), f2mul(gmgmk, cqx)), Rho);
            F2 c32 = f2sub(f2mul(gamm1, cpy), f2mul(Gmk, cqx));
            F2 gg   = f2mul(gmgmk, gm1sq);
            F2 gmk2 = f2mul(gmgmk, gmgmk);
            F2 g1q  = f2mul(gm1sq, gm1sq);
            F2 hh = f2fma(gmk2, xz, f2mul(g1q, wy));
            hh = f2fma(gg, A2, hh);
            F2 c40 = f2mul(hh, NRho2);
            F2 k1 = f2mul(f2mul(Gmk, gamm1), twgm1);
            F2 k2 = f2mul(gmgmk, Gmk);
            F2 k3 = f2mul(gamm1, gm1sq);
            F2 v2 = f2fma(k2, xz, f2mul(k3, wy));
            v2 = f2fma(k1, a0pq, v2);
            F2 c42 = f2mul(v2, NRho);
            F2 c20 = f2mul(Tp, c42), c21 = f2mul(Tp, c32);
            F2 c23 = f2mul(Tp, c12), c24 = f2mul(Tp, c02);
            F2 dd = f2sub(cpcq, c00);
            F2 c22 = f2add(A0, f2add(dd, dd));

            F2 ee0 = f2fma(E0, c00, f2fma(E1, c10, f2fma(E2, c20, f2fma(E3, c30, f2mul(E4, c40)))));
            F2 ee1 = f2fma(E0, c01, f2fma(E1, cpcq, f2fma(E2, c21, f2sub(f2mul(E4, c30), f2mul(E3, xy)))));
            F2 ee2 = f2fma(E0, c02, f2fma(E1, c12, f2fma(E2, c22, f2fma(E3, c32, f2mul(E4, c42)))));
            F2 ee3 = f2fma(E0, c03, f2fma(E2, c23, f2fma(E3, cpcq, f2sub(f2mul(E4, c10), f2mul(E1, wz)))));
            F2 ee4 = f2fma(E0, c04, f2fma(E1, c03, f2fma(E2, c24, f2fma(E3, c01, f2mul(E4, c00)))));

            if (do_norm) {
                float g0, q0, g1, q1, g2, q2, g3, q3, g4, q4;
                f2up(ee0, g0, q0); f2up(ee1, g1, q1); f2up(ee2, g2, q2);
                f2up(ee3, g3, q3); f2up(ee4, g4, q4);
                float t1a = fmaxf(fmaxf(fabsf(g0), fabsf(g1)),
                                  fmaxf(fmaxf(fabsf(g2), fabsf(g3)), fabsf(g4)));
                float t1b = fmaxf(fmaxf(fabsf(q0), fabsf(q1)),
                                  fmaxf(fmaxf(fabsf(q2), fabsf(q3)), fabsf(q4)));
                t1a = fmaxf(t1a, 1e-30f);
                t1b = fmaxf(t1b, 1e-30f);
                F2 Ti = f2pk(__fdividef(1.0f, t1a), __fdividef(1.0f, t1b));
                E0 = f2mul(ee0, Ti); E1 = f2mul(ee1, Ti); E2 = f2mul(ee2, Ti);
                E3 = f2mul(ee3, Ti); E4 = f2mul(ee4, Ti);
            } else {
                E0 = ee0; E1 = ee1; E2 = ee2; E3 = ee3; E4 = ee4;
            }
        };

        #pragma unroll 1
        for (int i = L_ - 2; i >= 1; i -= 2) {   // layers 30..1 in pairs
            step(i, false);
            step(i - 1, true);
        }
        step(0, true);                            // final layer always normalized

        float d0, d1;
        f2up(E0, d0, d1);
        if (is_e00) {
            g_e00[blk] = d0;
        } else {
            mn = fminf(mn, fminf(d0, d1));
            mx = fmaxf(mx, fmaxf(d0, d1));
        }
    }

    #pragma unroll
    for (int o = 16; o > 0; o >>= 1) {
        mn = fminf(mn, __shfl_xor_sync(0xffffffffu, mn, o));
        mx = fmaxf(mx, __shfl_xor_sync(0xffffffffu, mx, o));
    }
    int wid = threadIdx.x >> 5;
    if ((threadIdx.x & 31) == 0) { red[wid] = mn; red[wid + 32] = mx; }
    __syncthreads();
    if (threadIdx.x == 0) {
        float amn = red[0], amx = red[32];
        #pragma unroll
        for (int i = 1; i < 4; i++) {
            amn = fminf(amn, red[i]);
            amx = fmaxf(amx, red[i + 32]);
        }
        g_rng[blk] = amx - amn;
    }
}

// ---------------------------------------------------------------------------
__global__ void __launch_bounds__(128) finalKernel(const float* __restrict__ b,
                                                   float* __restrict__ out) {
    __shared__ float red[4];
    int m = blockIdx.x;
    float acc = 0.0f;
    for (int p = threadIdx.x; p < P_; p += blockDim.x) {
        int idx = m * P_ + p;
        float v = g_e00[idx] / g_rng[idx];
        float pw = __expf(-2.3025850929940457f * fabsf(v));   // 0.1^|v|
        acc += fabsf(pw - 1.0f);
    }
    acc *= (1.0f / (float)P_);
    for (int i = threadIdx.x; i < L_; i += blockDim.x) {
        float bi = b[m * L_ + i];
        float val;
        if (i == 0)            val = bi - b[m * L_ + 1];
        else if (i == L_ - 1)  val = bi - b[m * L_ + L_ - 2];
        else                   val = 2.0f * bi - b[m * L_ + i - 1] - b[m * L_ + i + 1];
        acc += fabsf(val) * (1.0f / (float)L_);
    }
    #pragma unroll
    for (int o = 16; o > 0; o >>= 1) acc += __shfl_xor_sync(0xffffffffu, acc, o);
    int wid = threadIdx.x >> 5;
    if ((threadIdx.x & 31) == 0) red[wid] = acc;
    __syncthreads();
    if (threadIdx.x == 0) out[m] = red[0] + red[1] + red[2] + red[3];
}

// ---------------------------------------------------------------------------
extern "C" void kernel_launch(void* const* d_in, const int* in_sizes, int n_in,
                              void* d_out, int out_size) {
    const float* vlist = (const float*)d_in[0];
    const float* tlist = (const float*)d_in[1];
    const float* d     = (const float*)d_in[2];
    const float* b     = (const float*)d_in[3];
    const float* Clist = (const float*)d_in[4];
    float* out = (float*)d_out;

    dummyKernel<<<1, 32>>>();
    dummyKernel<<<1, 32>>>();
    prepKernel<<<(M_ * L_ + 255) / 256, 256>>>(d, b);
    detKernel<<<M_ * P_, 128>>>(tlist, Clist, vlist);
    dummyKernel<<<1, 32>>>();   // keeps per-call launch count/positions stable for ncu -s
    finalKernel<<<M_, 128>>>(b, out);
}

// round 4
// speedup vs baseline: 1.3611x; 1.1360x over previous
#include <cuda_runtime.h>

#define M_   64
#define L_   32
#define P_   100
#define NC_  400
#define NPAIR_ (NC_/2)
#define PTS_PER_BLK 3
#define ITEMS_PER_PT (NPAIR_ + 1)          // 200 C-pairs + 1 e00
#define TWO_PI_F 6.28318530717958647692f

typedef unsigned long long ull;

struct Layer { float d, inv_a, inv_b, b2, rho, inv_rho; };

__device__ Layer g_layers[M_ * L_];
__device__ float g_rng[M_ * P_];
__device__ float g_e00[M_ * P_];

// ---------------------------------------------------------------------------
// Packed fp32x2 helpers
// ---------------------------------------------------------------------------
struct F2 { ull v; };
__device__ __forceinline__ F2 f2pk(float a, float b) {
    F2 r; asm("mov.b64 %0,{%1,%2};" : "=l"(r.v) : "f"(a), "f"(b)); return r;
}
__device__ __forceinline__ void f2up(F2 a, float& x, float& y) {
    asm("mov.b64 {%0,%1},%2;" : "=f"(x), "=f"(y) : "l"(a.v));
}
__device__ __forceinline__ F2 f2mul(F2 a, F2 b) {
    F2 r; asm("mul.rn.f32x2 %0,%1,%2;" : "=l"(r.v) : "l"(a.v), "l"(b.v)); return r;
}
__device__ __forceinline__ F2 f2add(F2 a, F2 b) {
    F2 r; asm("add.rn.f32x2 %0,%1,%2;" : "=l"(r.v) : "l"(a.v), "l"(b.v)); return r;
}
__device__ __forceinline__ F2 f2sub(F2 a, F2 b) {
    F2 r; asm("sub.rn.f32x2 %0,%1,%2;" : "=l"(r.v) : "l"(a.v), "l"(b.v)); return r;
}
__device__ __forceinline__ F2 f2fma(F2 a, F2 b, F2 c) {
    F2 r; asm("fma.rn.f32x2 %0,%1,%2,%3;" : "=l"(r.v) : "l"(a.v), "l"(b.v), "l"(c.v)); return r;
}
__device__ __forceinline__ float frsqa(float x) {
    float r; asm("rsqrt.approx.f32 %0,%1;" : "=f"(r) : "f"(x)); return r;
}
__device__ __forceinline__ float fsqrta(float x) {
    float r; asm("sqrt.approx.f32 %0,%1;" : "=f"(r) : "f"(x)); return r;
}
__device__ __forceinline__ ull dupf(float f) {
    unsigned u = __float_as_uint(f); return ((ull)u << 32) | (ull)u;
}
// order-preserving float<->uint mapping (monotone: bigger float <-> bigger uint)
__device__ __forceinline__ unsigned ford(float f) {
    unsigned u = __float_as_uint(f);
    return (u & 0x80000000u) ? ~u : (u | 0x80000000u);
}
__device__ __forceinline__ float funord(unsigned u) {
    return (u & 0x80000000u) ? __uint_as_float(u & 0x7FFFFFFFu) : __uint_as_float(~u);
}

// ---------------------------------------------------------------------------
// _var for one lane. Data-range facts (t>=0.5, C>=1.0, v>=1.2, d<=1.0):
// p,q <= 12.6 < 16 and exa <= ~26 < 60, so the reference's cutoff selects are
// no-ops and omitted. rsqrt replaces sqrt+rcp.
// ---------------------------------------------------------------------------
__device__ __forceinline__ void var_lane(
    float wv, float wv2, float dm, float xka, float xka2, float xkb, float xkb2,
    float& cosp, float& cosq, float& w, float& x, float& y, float& z, float& a0)
{
    float ra2 = fabsf(wv2 - xka2);
    float rb2 = fabsf(wv2 - xkb2);
    float ira = frsqa(ra2);                 // inf when ra2 == 0
    float irb = frsqa(rb2);
    float ra = (ra2 > 0.0f) ? ra2 * ira : 0.0f;
    float rb = (rb2 > 0.0f) ? rb2 * irb : 0.0f;
    float p = ra * dm, q = rb * dm;
    float sinp, cosp_o; __sincosf(p, &sinp, &cosp_o);
    float sinq, cosq_o; __sincosf(q, &sinq, &cosq_o);
    float fac_p = __expf(-2.0f * p);
    float fac_q = __expf(-2.0f * q);
    float cosp_e = fmaf(0.5f, fac_p, 0.5f), sinp_e = fmaf(-0.5f, fac_p, 0.5f);
    float cosq_e = fmaf(0.5f, fac_q, 0.5f), sinq_e = fmaf(-0.5f, fac_q, 0.5f);
    bool lt_a = wv < xka, gt_a = wv > xka;
    bool lt_b = wv < xkb, gt_b = wv > xkb;
    float pex = lt_a ? 0.0f : p;
    float sex = lt_b ? 0.0f : q;
    cosp = lt_a ? cosp_o : cosp_e;
    cosq = lt_b ? cosq_o : cosq_e;
    // eq-case: NaN/inf from ira discarded by the dm select.
    w = lt_a ? sinp * ira : (gt_a ? sinp_e * ira : dm);
    x = lt_a ? -ra * sinp : ra * sinp_e;
    y = lt_b ? sinq * irb : (gt_b ? sinq_e * irb : dm);
    z = lt_b ? -rb * sinq : rb * sinq_e;
    a0 = __expf(-(pex + sex));
}

__device__ __forceinline__ void half_lane(
    float wv2, float xka2h, float xkb2h, float gmkh, float rhoh,
    float& e0, float& e1, float& e2, float& e3, float& e4)
{
    float ra = fsqrta(fabsf(wv2 - xka2h));
    float rb = fsqrta(fabsf(wv2 - xkb2h));
    float gam = gmkh * wv2, gamm1 = gam - 1.0f;
    float rarb = ra * rb;
    e0 = rhoh * rhoh * (gamm1 * gamm1 - gam * gmkh * rarb);
    e1 = -rhoh * ra;
    e2 = rhoh * (gamm1 - gmkh * rarb);
    e3 = rhoh * rb;
    e4 = wv2 - rarb;
}

// ---------------------------------------------------------------------------
__global__ void prepKernel(const float* __restrict__ d, const float* __restrict__ b) {
    int i = blockIdx.x * blockDim.x + threadIdx.x;
    if (i >= M_ * L_) return;
    float bb = b[i];
    float b2 = bb * bb, b3 = b2 * bb, b4 = b2 * b2;
    float a = 0.9409f + 2.0947f * bb - 0.8206f * b2 + 0.2683f * b3 - 0.0251f * b4;
    float a2 = a * a, a3 = a2 * a, a4 = a2 * a2, a5 = a4 * a;
    float rho = 1.6612f * a - 0.4721f * a2 + 0.0671f * a3 - 0.0043f * a4 + 0.000106f * a5;
    Layer ly;
    ly.d = d[i]; ly.inv_a = 1.0f / a; ly.inv_b = 1.0f / bb;
    ly.b2 = b2;  ly.rho = rho;        ly.inv_rho = 1.0f / rho;
    g_layers[i] = ly;
}

__global__ void dummyKernel() {}   // ncu capture alignment

// ---------------------------------------------------------------------------
// Det grid: one block serves PTS_PER_BLK (m,p) points -> 603 items over 128
// threads in 5 strided passes (94% lane utilization). Per-point rng via
// shared atomics on order-mapped uints. e00 item folded in per point.
// ---------------------------------------------------------------------------
__global__ void __launch_bounds__(128, 6) detKernel(const float* __restrict__ tlist,
                                                    const float* __restrict__ Clist,
                                                    const float* __restrict__ vlist) {
    __shared__ float sD[PTS_PER_BLK * L_], sXka[PTS_PER_BLK * L_], sXka2[PTS_PER_BLK * L_];
    __shared__ float sXkb[PTS_PER_BLK * L_], sXkb2[PTS_PER_BLK * L_];
    __shared__ ull pGmk[PTS_PER_BLK * L_], pRho[PTS_PER_BLK * L_], pNRho[PTS_PER_BLK * L_],
                   pNRho2[PTS_PER_BLK * L_], pRhoI[PTS_PER_BLK * L_], pNRhoI[PTS_PER_BLK * L_],
                   pNRhoI2[PTS_PER_BLK * L_];
    __shared__ float sGmkH[PTS_PER_BLK], sRhoH[PTS_PER_BLK];
    __shared__ float sOmg[PTS_PER_BLK], sV[PTS_PER_BLK];
    __shared__ unsigned sMnU[PTS_PER_BLK], sMxU[PTS_PER_BLK];
    __shared__ float shC[NC_];

    int tid = threadIdx.x;
    int p0 = blockIdx.x * PTS_PER_BLK;
    int npts = min(PTS_PER_BLK, M_ * P_ - p0);

    if (tid < npts) {
        sOmg[tid] = TWO_PI_F / tlist[p0 + tid];
        sV[tid] = vlist[p0 + tid];
        sMnU[tid] = 0xFFFFFFFFu;
        sMxU[tid] = 0u;
    }
    for (int i = tid; i < npts * L_; i += 128) {
        int s = i >> 5, l = i & 31;
        int pt = p0 + s;
        float omega = fmaxf(TWO_PI_F / tlist[pt], 1e-4f);
        Layer ly = g_layers[(pt / P_) * L_ + l];
        float xka = omega * ly.inv_a, xkb = omega * ly.inv_b;
        float iw = __fdividef(1.0f, omega);
        float gmk = 2.0f * ly.b2 * iw * iw;
        sD[i] = ly.d; sXka[i] = xka; sXka2[i] = xka * xka;
        sXkb[i] = xkb; sXkb2[i] = xkb * xkb;
        pGmk[i]    = dupf(gmk);
        pRho[i]    = dupf(ly.rho);
        pNRho[i]   = dupf(-ly.rho);
        pNRho2[i]  = dupf(-ly.rho * ly.rho);
        pRhoI[i]   = dupf(ly.inv_rho);
        pNRhoI[i]  = dupf(-ly.inv_rho);
        pNRhoI2[i] = dupf(-ly.inv_rho * ly.inv_rho);
        if (l == L_ - 1) { sGmkH[s] = gmk; sRhoH[s] = ly.rho; }
    }
    for (int i = tid; i < NC_; i += 128) shC[i] = Clist[i];
    __syncthreads();

    int nit = npts * ITEMS_PER_PT;
    #pragma unroll 1
    for (int it = tid; it < nit; it += 128) {
        int j = (it >= 2 * ITEMS_PER_PT) ? 2 : ((it >= ITEMS_PER_PT) ? 1 : 0);
        int local = it - j * ITEMS_PER_PT;
        int jo = j << 5;
        bool is_e00 = (local == NPAIR_);
        float omega_raw = sOmg[j];
        float den0 = is_e00 ? sV[j] : shC[2 * local];
        float den1 = is_e00 ? sV[j] : shC[2 * local + 1];
        float wv0 = __fdividef(omega_raw, den0);
        float wv1 = __fdividef(omega_raw, den1);
        float wv20 = wv0 * wv0, wv21 = wv1 * wv1;
        F2 W2 = f2pk(wv20, wv21);
        F2 Tp = f2pk(-2.0f * wv20, -2.0f * wv21);
        F2 ONE = f2pk(1.0f, 1.0f);

        float xka2_h = sXka2[jo + L_ - 1], xkb2_h = sXkb2[jo + L_ - 1];
        float gmk_h = sGmkH[j], rho_h = sRhoH[j];
        float h0a, h1a, h2a, h3a, h4a, h0b, h1b, h2b, h3b, h4b;
        half_lane(wv20, xka2_h, xkb2_h, gmk_h, rho_h, h0a, h1a, h2a, h3a, h4a);
        half_lane(wv21, xka2_h, xkb2_h, gmk_h, rho_h, h0b, h1b, h2b, h3b, h4b);
        F2 E0 = f2pk(h0a, h0b), E1 = f2pk(h1a, h1b), E2 = f2pk(h2a, h2b);
        F2 E3 = f2pk(h3a, h3b), E4 = f2pk(h4a, h4b);

        auto step = [&](int i, bool do_norm) {
            int li = jo + i;
            float dm = sD[li], xka = sXka[li], xka2 = sXka2[li], xkb = sXkb[li], xkb2 = sXkb2[li];
            float cp0, cq0, w0, x0, y0, z0, a00;
            float cp1, cq1, w1, x1, y1, z1, a01;
            var_lane(wv0, wv20, dm, xka, xka2, xkb, xkb2, cp0, cq0, w0, x0, y0, z0, a00);
            var_lane(wv1, wv21, dm, xka, xka2, xkb, xkb2, cp1, cq1, w1, x1, y1, z1, a01);
            F2 Cp = f2pk(cp0, cp1), Cq = f2pk(cq0, cq1);
            F2 W = f2pk(w0, w1), X = f2pk(x0, x1), Y = f2pk(y0, y1), Z = f2pk(z0, z1);
            F2 A0 = f2pk(a00, a01);

            F2 Gmk;    Gmk.v    = pGmk[li];
            F2 Rho;    Rho.v    = pRho[li];
            F2 NRho;   NRho.v   = pNRho[li];
            F2 NRho2;  NRho2.v  = pNRho2[li];
            F2 RhoI;   RhoI.v   = pRhoI[li];
            F2 NRhoI;  NRhoI.v  = pNRhoI[li];
            F2 NRhoI2; NRhoI2.v = pNRhoI2[li];

            F2 Gam  = f2mul(Gmk, W2);
            F2 cpcq = f2mul(Cp, Cq);
            F2 cpy = f2mul(Cp, Y), cpz = f2mul(Cp, Z);
            F2 cqw = f2mul(Cq, W), cqx = f2mul(Cq, X);
            F2 xy = f2mul(X, Y), xz = f2mul(X, Z), wy = f2mul(W, Y), wz = f2mul(W, Z);
            F2 gamm1 = f2sub(Gam, ONE);
            F2 twgm1 = f2add(Gam, gamm1);
            F2 gmgmk = f2mul(Gam, Gmk);
            F2 gmgm1 = f2mul(Gam, gamm1);
            F2 gm1sq = f2mul(gamm1, gamm1);
            F2 a0pq  = f2sub(A0, cpcq);
            F2 A2    = f2add(a0pq, a0pq);
            F2 w2wy  = f2mul(W2, wy);

            F2 u = f2fma(gm1sq, w2wy, f2mul(gmgmk, xz));
            u = f2fma(gmgm1, A2, u);
            F2 c00 = f2sub(cpcq, u);
            F2 c01 = f2mul(f2sub(f2mul(W2, cpy), cqx), RhoI);
            F2 v = f2fma(Gmk, xz, f2mul(gamm1, w2wy));
            v = f2fma(twgm1, a0pq, v);
            F2 c02 = f2mul(v, NRhoI);
            F2 c03 = f2mul(f2sub(cpz, f2mul(W2, cqw)), RhoI);
            F2 s = f2fma(W2, A2, xz);
            s = f2fma(W2, w2wy, s);
            F2 c04 = f2mul(s, NRhoI2);
            F2 c10 = f2mul(f2sub(f2mul(gmgmk, cpz), f2mul(gm1sq, cqw)), Rho);
            F2 c12 = f2sub(f2mul(Gmk, cpz), f2mul(gamm1, cqw));
            F2 c30 = f2mul(f2sub(f2mul(gm1sq, cpy), f2mul(gmgmk, cqx)), Rho);
            F2 c32 = f2sub(f2mul(gamm1, cpy), f2mul(Gmk, cqx));
            F2 gg   = f2mul(gmgmk, gm1sq);
            F2 gmk2 = f2mul(gmgmk, gmgmk);
            F2 g1q  = f2mul(gm1sq, gm1sq);
            F2 hh = f2fma(gmk2, xz, f2mul(g1q, wy));
            hh = f2fma(gg, A2, hh);
            F2 c40 = f2mul(hh, NRho2);
            F2 k1 = f2mul(f2mul(Gmk, gamm1), twgm1);
            F2 k2 = f2mul(gmgmk, Gmk);
            F2 k3 = f2mul(gamm1, gm1sq);
            F2 v2 = f2fma(k2, xz, f2mul(k3, wy));
            v2 = f2fma(k1, a0pq, v2);
            F2 c42 = f2mul(v2, NRho);
            F2 c20 = f2mul(Tp, c42), c21 = f2mul(Tp, c32);
            F2 c23 = f2mul(Tp, c12), c24 = f2mul(Tp, c02);
            F2 dd = f2sub(cpcq, c00);
            F2 c22 = f2add(A0, f2add(dd, dd));

            F2 ee0 = f2fma(E0, c00, f2fma(E1, c10, f2fma(E2, c20, f2fma(E3, c30, f2mul(E4, c40)))));
            F2 ee1 = f2fma(E0, c01, f2fma(E1, cpcq, f2fma(E2, c21, f2sub(f2mul(E4, c30), f2mul(E3, xy)))));
            F2 ee2 = f2fma(E0, c02, f2fma(E1, c12, f2fma(E2, c22, f2fma(E3, c32, f2mul(E4, c42)))));
            F2 ee3 = f2fma(E0, c03, f2fma(E2, c23, f2fma(E3, cpcq, f2sub(f2mul(E4, c10), f2mul(E1, wz)))));
            F2 ee4 = f2fma(E0, c04, f2fma(E1, c03, f2fma(E2, c24, f2fma(E3, c01, f2mul(E4, c00)))));

            if (do_norm) {
                float g0, q0, g1, q1, g2, q2, g3, q3, g4, q4;
                f2up(ee0, g0, q0); f2up(ee1, g1, q1); f2up(ee2, g2, q2);
                f2up(ee3, g3, q3); f2up(ee4, g4, q4);
                float t1a = fmaxf(fmaxf(fabsf(g0), fabsf(g1)),
                                  fmaxf(fmaxf(fabsf(g2), fabsf(g3)), fabsf(g4)));
                float t1b = fmaxf(fmaxf(fabsf(q0), fabsf(q1)),
                                  fmaxf(fmaxf(fabsf(q2), fabsf(q3)), fabsf(q4)));
                t1a = fmaxf(t1a, 1e-30f);
                t1b = fmaxf(t1b, 1e-30f);
                F2 Ti = f2pk(__fdividef(1.0f, t1a), __fdividef(1.0f, t1b));
                E0 = f2mul(ee0, Ti); E1 = f2mul(ee1, Ti); E2 = f2mul(ee2, Ti);
                E3 = f2mul(ee3, Ti); E4 = f2mul(ee4, Ti);
            } else {
                E0 = ee0; E1 = ee1; E2 = ee2; E3 = ee3; E4 = ee4;
            }
        };

        #pragma unroll 1
        for (int i = L_ - 2; i >= 1; i -= 2) {
            step(i, false);
            step(i - 1, true);
        }
        step(0, true);

        float d0, d1;
        f2up(E0, d0, d1);
        if (is_e00) {
            g_e00[p0 + j] = d0;
        } else {
            float lo = fminf(d0, d1), hi = fmaxf(d0, d1);
            atomicMin(&sMnU[j], ford(lo));
            atomicMax(&sMxU[j], ford(hi));
        }
    }
    __syncthreads();
    if (tid < npts) {
        g_rng[p0 + tid] = funord(sMxU[tid]) - funord(sMnU[tid]);
    }
}

// ---------------------------------------------------------------------------
__global__ void __launch_bounds__(128) finalKernel(const float* __restrict__ b,
                                                   float* __restrict__ out) {
    __shared__ float red[4];
    int m = blockIdx.x;
    float acc = 0.0f;
    for (int p = threadIdx.x; p < P_; p += blockDim.x) {
        int idx = m * P_ + p;
        float v = g_e00[idx] / g_rng[idx];
        float pw = __expf(-2.3025850929940457f * fabsf(v));   // 0.1^|v|
        acc += fabsf(pw - 1.0f);
    }
    acc *= (1.0f / (float)P_);
    for (int i = threadIdx.x; i < L_; i += blockDim.x) {
        float bi = b[m * L_ + i];
        float val;
        if (i == 0)            val = bi - b[m * L_ + 1];
        else if (i == L_ - 1)  val = bi - b[m * L_ + L_ - 2];
        else                   val = 2.0f * bi - b[m * L_ + i - 1] - b[m * L_ + i + 1];
        acc += fabsf(val) * (1.0f / (float)L_);
    }
    #pragma unroll
    for (int o = 16; o > 0; o >>= 1) acc += __shfl_xor_sync(0xffffffffu, acc, o);
    int wid = threadIdx.x >> 5;
    if ((threadIdx.x & 31) == 0) red[wid] = acc;
    __syncthreads();
    if (threadIdx.x == 0) out[m] = red[0] + red[1] + red[2] + red[3];
}

// ---------------------------------------------------------------------------
extern "C" void kernel_launch(void* const* d_in, const int* in_sizes, int n_in,
                              void* d_out, int out_size) {
    const float* vlist = (const float*)d_in[0];
    const float* tlist = (const float*)d_in[1];
    const float* d     = (const float*)d_in[2];
    const float* b     = (const float*)d_in[3];
    const float* Clist = (const float*)d_in[4];
    float* out = (float*)d_out;

    dummyKernel<<<1, 32>>>();
    dummyKernel<<<1, 32>>>();
    prepKernel<<<(M_ * L_ + 255) / 256, 256>>>(d, b);
    int nblk = (M_ * P_ + PTS_PER_BLK - 1) / PTS_PER_BLK;
    detKernel<<<nblk, 128>>>(tlist, Clist, vlist);
    dummyKernel<<<1, 32>>>();   // keeps launch positions stable for ncu -s
    finalKernel<<<M_, 128>>>(b, out);
}